// round 1
// baseline (speedup 1.0000x reference)
#include <cuda_runtime.h>
#include <math.h>
#include <float.h>

#define B_   4
#define CIN  256
#define CP   128
#define NS   4096

// ---- scratch (static device globals; no allocation allowed) ----
__device__ float g_t[B_*CP*NS];
__device__ float g_p[B_*CP*NS];
__device__ float g_g[B_*CP*NS];
__device__ float g_y[B_*CP*NS];
__device__ float g_z[B_*CIN*NS];
__device__ float g_s[(size_t)B_*NS*NS];        // attention logits s[b][m][n], 268 MB
__device__ float g_rowmax[B_*NS];
__device__ float g_rowsuminv[B_*NS];
__device__ float g_mean[CIN];
__device__ float g_invstd[CIN];

// ============================================================================
// Kernel 1: projections t/p/g = W @ x  (NN SGEMM, M=128, K=256, N=4096)
// grid (32, 3, 4): x=n-tile, y=which weight, z=batch
// ============================================================================
__global__ __launch_bounds__(256) void proj_kernel(
    const float* __restrict__ x,
    const float* __restrict__ Wt, const float* __restrict__ Wp,
    const float* __restrict__ Wg)
{
    const int b = blockIdx.z;
    const int w = blockIdx.y;
    const float* A = (w == 0) ? Wt : (w == 1) ? Wp : Wg;   // [CP, CIN] k-contig
    float* Cout = ((w == 0) ? g_t : (w == 1) ? g_p : g_g) + (size_t)b*CP*NS;
    const float* Bm = x + (size_t)b*CIN*NS;                 // [CIN, NS]
    const int n0 = blockIdx.x * 128;

    __shared__ float As[16][128];
    __shared__ float Bs[16][128];
    float acc[8][8] = {};

    const int tid  = threadIdx.x;
    const int trow = tid / 16, tcol = tid % 16;
    const int aRow = tid >> 2,  aCol = (tid & 3) * 4;
    const int bRow = tid >> 5,  bCol = (tid & 31) * 4;

    for (int k0 = 0; k0 < CIN; k0 += 16) {
        #pragma unroll
        for (int r = 0; r < 2; r++) {
            int row = aRow + r*64;
            float4 v = *(const float4*)(A + (size_t)row*CIN + k0 + aCol);
            As[aCol+0][row] = v.x; As[aCol+1][row] = v.y;
            As[aCol+2][row] = v.z; As[aCol+3][row] = v.w;
        }
        #pragma unroll
        for (int r = 0; r < 2; r++) {
            int krow = bRow + r*8;
            *(float4*)&Bs[krow][bCol] =
                *(const float4*)(Bm + (size_t)(k0+krow)*NS + n0 + bCol);
        }
        __syncthreads();
        #pragma unroll
        for (int kk = 0; kk < 16; kk++) {
            float a[8], bb[8];
            #pragma unroll
            for (int i = 0; i < 8; i++) a[i]  = As[kk][trow*8 + i];
            #pragma unroll
            for (int j = 0; j < 8; j++) bb[j] = Bs[kk][tcol*8 + j];
            #pragma unroll
            for (int i = 0; i < 8; i++)
                #pragma unroll
                for (int j = 0; j < 8; j++) acc[i][j] += a[i]*bb[j];
        }
        __syncthreads();
    }
    #pragma unroll
    for (int i = 0; i < 8; i++) {
        int row = trow*8 + i;
        #pragma unroll
        for (int j = 0; j < 8; j += 4) {
            float4 v = make_float4(acc[i][j], acc[i][j+1], acc[i][j+2], acc[i][j+3]);
            *(float4*)(Cout + (size_t)row*NS + n0 + tcol*8 + j) = v;
        }
    }
}

// ============================================================================
// Kernel 2: s[b][m][n] = sum_c p[b][c][m] * t[b][c][n]   (TN SGEMM, K=128)
// grid (32, 32, 4): x=n-tile, y=m-tile, z=batch
// ============================================================================
__global__ __launch_bounds__(256) void att_logits_kernel()
{
    const int b = blockIdx.z;
    const float* A  = g_p + (size_t)b*CP*NS;   // [K=CP][NS] m-contig
    const float* Bm = g_t + (size_t)b*CP*NS;   // [K=CP][NS] n-contig
    float* Cout = g_s + (size_t)b*NS*NS;
    const int m0 = blockIdx.y * 128;
    const int n0 = blockIdx.x * 128;

    __shared__ float As[16][128];
    __shared__ float Bs[16][128];
    float acc[8][8] = {};

    const int tid  = threadIdx.x;
    const int trow = tid / 16, tcol = tid % 16;
    const int bRow = tid >> 5, bCol = (tid & 31) * 4;

    for (int k0 = 0; k0 < CP; k0 += 16) {
        #pragma unroll
        for (int r = 0; r < 2; r++) {
            int krow = bRow + r*8;
            *(float4*)&As[krow][bCol] =
                *(const float4*)(A  + (size_t)(k0+krow)*NS + m0 + bCol);
            *(float4*)&Bs[krow][bCol] =
                *(const float4*)(Bm + (size_t)(k0+krow)*NS + n0 + bCol);
        }
        __syncthreads();
        #pragma unroll
        for (int kk = 0; kk < 16; kk++) {
            float a[8], bb[8];
            #pragma unroll
            for (int i = 0; i < 8; i++) a[i]  = As[kk][trow*8 + i];
            #pragma unroll
            for (int j = 0; j < 8; j++) bb[j] = Bs[kk][tcol*8 + j];
            #pragma unroll
            for (int i = 0; i < 8; i++)
                #pragma unroll
                for (int j = 0; j < 8; j++) acc[i][j] += a[i]*bb[j];
        }
        __syncthreads();
    }
    #pragma unroll
    for (int i = 0; i < 8; i++) {
        int row = m0 + trow*8 + i;
        #pragma unroll
        for (int j = 0; j < 8; j += 4) {
            float4 v = make_float4(acc[i][j], acc[i][j+1], acc[i][j+2], acc[i][j+3]);
            *(float4*)(Cout + (size_t)row*NS + n0 + tcol*8 + j) = v;
        }
    }
}

// ============================================================================
// Kernel 3: per-row (b,m) softmax stats over n:  max, 1/sum(exp)
// grid: B_*NS blocks, 256 threads
// ============================================================================
__global__ __launch_bounds__(256) void row_stats_kernel()
{
    const size_t row = blockIdx.x;
    const float* rp = g_s + row * NS;
    __shared__ float sh[NS];
    __shared__ float red[256];
    const int tid = threadIdx.x;

    float mx = -FLT_MAX;
    for (int i = tid; i < NS; i += 256) { float v = rp[i]; sh[i] = v; mx = fmaxf(mx, v); }
    red[tid] = mx; __syncthreads();
    #pragma unroll
    for (int s = 128; s > 0; s >>= 1) {
        if (tid < s) red[tid] = fmaxf(red[tid], red[tid + s]);
        __syncthreads();
    }
    const float m = red[0];
    __syncthreads();

    float ssum = 0.f;
    for (int i = tid; i < NS; i += 256) ssum += __expf(sh[i] - m);
    red[tid] = ssum; __syncthreads();
    #pragma unroll
    for (int s = 128; s > 0; s >>= 1) {
        if (tid < s) red[tid] += red[tid + s];
        __syncthreads();
    }
    if (tid == 0) { g_rowmax[row] = m; g_rowsuminv[row] = 1.0f / red[0]; }
}

// ============================================================================
// Kernel 4: y[b][c][n] = sum_m (g[b][c][m]/L[m]) * exp(s[b][m][n] - M[m])
// NN SGEMM with load-time transforms, M=128, K=4096, N=4096
// grid (32, 1, 4)
// ============================================================================
__global__ __launch_bounds__(256) void attn_apply_kernel()
{
    const int b = blockIdx.z;
    const float* A    = g_g + (size_t)b*CP*NS;   // [CP][K=NS] k-contig
    const float* Bm   = g_s + (size_t)b*NS*NS;   // [K=NS][NS]
    const float* rmax = g_rowmax    + (size_t)b*NS;
    const float* rinv = g_rowsuminv + (size_t)b*NS;
    float* Cout = g_y + (size_t)b*CP*NS;
    const int n0 = blockIdx.x * 128;

    __shared__ float As[16][128];
    __shared__ float Bs[16][128];
    float acc[8][8] = {};

    const int tid  = threadIdx.x;
    const int trow = tid / 16, tcol = tid % 16;
    const int aRow = tid >> 2,  aCol = (tid & 3) * 4;
    const int bRow = tid >> 5,  bCol = (tid & 31) * 4;

    for (int k0 = 0; k0 < NS; k0 += 16) {
        float4 rv = *(const float4*)(rinv + k0 + aCol);
        #pragma unroll
        for (int r = 0; r < 2; r++) {
            int row = aRow + r*64;
            float4 v = *(const float4*)(A + (size_t)row*NS + k0 + aCol);
            As[aCol+0][row] = v.x * rv.x; As[aCol+1][row] = v.y * rv.y;
            As[aCol+2][row] = v.z * rv.z; As[aCol+3][row] = v.w * rv.w;
        }
        #pragma unroll
        for (int r = 0; r < 2; r++) {
            int krow = bRow + r*8;
            int kg = k0 + krow;
            float mr = rmax[kg];
            float4 v = *(const float4*)(Bm + (size_t)kg*NS + n0 + bCol);
            Bs[krow][bCol+0] = __expf(v.x - mr);
            Bs[krow][bCol+1] = __expf(v.y - mr);
            Bs[krow][bCol+2] = __expf(v.z - mr);
            Bs[krow][bCol+3] = __expf(v.w - mr);
        }
        __syncthreads();
        #pragma unroll
        for (int kk = 0; kk < 16; kk++) {
            float a[8], bb[8];
            #pragma unroll
            for (int i = 0; i < 8; i++) a[i]  = As[kk][trow*8 + i];
            #pragma unroll
            for (int j = 0; j < 8; j++) bb[j] = Bs[kk][tcol*8 + j];
            #pragma unroll
            for (int i = 0; i < 8; i++)
                #pragma unroll
                for (int j = 0; j < 8; j++) acc[i][j] += a[i]*bb[j];
        }
        __syncthreads();
    }
    #pragma unroll
    for (int i = 0; i < 8; i++) {
        int row = trow*8 + i;
        #pragma unroll
        for (int j = 0; j < 8; j += 4) {
            float4 v = make_float4(acc[i][j], acc[i][j+1], acc[i][j+2], acc[i][j+3]);
            *(float4*)(Cout + (size_t)row*NS + n0 + tcol*8 + j) = v;
        }
    }
}

// ============================================================================
// Kernel 5: z = Wz @ y   (NN SGEMM, M=256, K=128, N=4096)
// grid (32, 2, 4)
// ============================================================================
__global__ __launch_bounds__(256) void z_gemm_kernel(const float* __restrict__ Wz)
{
    const int b = blockIdx.z;
    const float* Bm = g_y + (size_t)b*CP*NS;    // [CP][NS]
    float* Cout = g_z + (size_t)b*CIN*NS;
    const int m0 = blockIdx.y * 128;
    const int n0 = blockIdx.x * 128;

    __shared__ float As[16][128];
    __shared__ float Bs[16][128];
    float acc[8][8] = {};

    const int tid  = threadIdx.x;
    const int trow = tid / 16, tcol = tid % 16;
    const int aRow = tid >> 2,  aCol = (tid & 3) * 4;
    const int bRow = tid >> 5,  bCol = (tid & 31) * 4;

    for (int k0 = 0; k0 < CP; k0 += 16) {
        #pragma unroll
        for (int r = 0; r < 2; r++) {
            int row = aRow + r*64;
            float4 v = *(const float4*)(Wz + (size_t)(m0+row)*CP + k0 + aCol);
            As[aCol+0][row] = v.x; As[aCol+1][row] = v.y;
            As[aCol+2][row] = v.z; As[aCol+3][row] = v.w;
        }
        #pragma unroll
        for (int r = 0; r < 2; r++) {
            int krow = bRow + r*8;
            *(float4*)&Bs[krow][bCol] =
                *(const float4*)(Bm + (size_t)(k0+krow)*NS + n0 + bCol);
        }
        __syncthreads();
        #pragma unroll
        for (int kk = 0; kk < 16; kk++) {
            float a[8], bb[8];
            #pragma unroll
            for (int i = 0; i < 8; i++) a[i]  = As[kk][trow*8 + i];
            #pragma unroll
            for (int j = 0; j < 8; j++) bb[j] = Bs[kk][tcol*8 + j];
            #pragma unroll
            for (int i = 0; i < 8; i++)
                #pragma unroll
                for (int j = 0; j < 8; j++) acc[i][j] += a[i]*bb[j];
        }
        __syncthreads();
    }
    #pragma unroll
    for (int i = 0; i < 8; i++) {
        int row = m0 + trow*8 + i;
        #pragma unroll
        for (int j = 0; j < 8; j += 4) {
            float4 v = make_float4(acc[i][j], acc[i][j+1], acc[i][j+2], acc[i][j+3]);
            *(float4*)(Cout + (size_t)row*NS + n0 + tcol*8 + j) = v;
        }
    }
}

// ============================================================================
// Kernel 6: BatchNorm stats per channel over (B, N)
// grid: CIN blocks, 256 threads
// ============================================================================
__global__ __launch_bounds__(256) void bn_reduce_kernel()
{
    const int c = blockIdx.x;
    const int tid = threadIdx.x;
    float s = 0.f, s2 = 0.f;
    for (int b = 0; b < B_; b++) {
        const float* zp = g_z + ((size_t)b*CIN + c) * NS;
        for (int i = tid; i < NS; i += 256) { float v = zp[i]; s += v; s2 += v*v; }
    }
    __shared__ float r1[256], r2[256];
    r1[tid] = s; r2[tid] = s2; __syncthreads();
    #pragma unroll
    for (int st = 128; st > 0; st >>= 1) {
        if (tid < st) { r1[tid] += r1[tid+st]; r2[tid] += r2[tid+st]; }
        __syncthreads();
    }
    if (tid == 0) {
        const float inv_n = 1.0f / (float)(B_*NS);
        float mean = r1[0] * inv_n;
        float var  = r2[0] * inv_n - mean*mean;
        g_mean[c]   = mean;
        g_invstd[c] = rsqrtf(var + 1e-5f);
    }
}

// ============================================================================
// Kernel 7: out = (z - mean)*invstd*gamma + beta + x
// ============================================================================
__global__ __launch_bounds__(512) void bn_apply_kernel(
    const float* __restrict__ x, const float* __restrict__ gamma,
    const float* __restrict__ beta, float* __restrict__ out)
{
    size_t idx = (size_t)blockIdx.x * blockDim.x + threadIdx.x;
    if (idx >= (size_t)B_*CIN*NS) return;
    int c = (int)((idx / NS) % CIN);
    out[idx] = (g_z[idx] - g_mean[c]) * g_invstd[c] * gamma[c] + beta[c] + x[idx];
}

// ============================================================================
extern "C" void kernel_launch(void* const* d_in, const int* in_sizes, int n_in,
                              void* d_out, int out_size)
{
    const float* x     = (const float*)d_in[0];
    const float* Wt    = (const float*)d_in[1];
    const float* Wp    = (const float*)d_in[2];
    const float* Wg    = (const float*)d_in[3];
    const float* Wz    = (const float*)d_in[4];
    const float* gamma = (const float*)d_in[5];
    const float* beta  = (const float*)d_in[6];
    float* out = (float*)d_out;

    proj_kernel      <<<dim3(32, 3, 4),  256>>>(x, Wt, Wp, Wg);
    att_logits_kernel<<<dim3(32, 32, 4), 256>>>();
    row_stats_kernel <<<B_*NS,           256>>>();
    attn_apply_kernel<<<dim3(32, 1, 4),  256>>>();
    z_gemm_kernel    <<<dim3(32, 2, 4),  256>>>(Wz);
    bn_reduce_kernel <<<CIN,             256>>>();
    const int total = B_*CIN*NS;
    bn_apply_kernel  <<<(total + 511)/512, 512>>>(x, gamma, beta, out);
}